// round 12
// baseline (speedup 1.0000x reference)
#include <cuda_runtime.h>

// B=16, C=2048, H=2, HS=64, HOD=1, D_MODEL=2
// Collapsed: M_h = Wq_h Wk_h^T (2x2), g_h = Wv_h Wo_h (2,)
//   t(c,f) = xp_c^T M_h xp_f / 8;  o_h(c) = sum_{f<=c} e^t (g_h.xp_f) / sum e^t
// Taylor degree 10: e^{p.y} = sum_{j+i<=10} (p0^j/j!)(p1^i/i!) y0^j y1^i
// => causal sums = polynomial in prefix moments M_{j,i} = sum_f y0^j y1^i (j+i<=11).
// Chunk = 32 f. K1 (128 x 640): power tables -> one dot per (chunk, moment).
// K2 (128 x 1024): float4 MLP prefix (g_mom transposed), row-factored poly,
// exact tails <= 32 iterations (uniform across tail warps).

#define CC    2048
#define NMOM  78            // #{(j,i): j+i<=11}
#define LOG2E 1.4426950408889634f

__device__ float g_mom[16][NMOM][64];   // [batch][moment][chunk32]  (chunk-contiguous)

__device__ __forceinline__ float ex2f(float v) {
    float y;
    asm("ex2.approx.ftz.f32 %0, %1;" : "=f"(y) : "f"(v));
    return y;
}

// ---------------- K1: chunk moments via smem power tables ----------------
// grid = 128 (b = bid>>3, window r = bid&7), 640 threads.
__global__ __launch_bounds__(640, 1)
void k1_moments(const float* __restrict__ x)
{
    __shared__ float sP0[8][12][33];   // y0^j per chunk32, pad 33 (conflict-free)
    __shared__ float sP1[8][12][33];   // y1^i

    const int tid = threadIdx.x;
    const int b   = blockIdx.x >> 3;
    const int r   = blockIdx.x & 7;

    if (tid < 256) {
        const int ch = tid >> 5, fl = tid & 31;
        const int f  = r * 256 + tid;
        const float2 v = reinterpret_cast<const float2*>(x)[b * CC + f];
        const float y0 = v.x + sinf((float)f);
        const float y1 = v.y + cosf((float)f);
        float p = 1.f, q = 1.f;
        #pragma unroll
        for (int j = 0; j < 12; ++j) {
            sP0[ch][j][fl] = p;  p *= y0;
            sP1[ch][j][fl] = q;  q *= y1;
        }
    }
    __syncthreads();

    if (tid < 8 * NMOM) {              // 624 dot threads
        const int ch = tid / NMOM;
        const int m  = tid % NMOM;
        int j = 0, mm = m;
        while (mm >= 12 - j) { mm -= 12 - j; ++j; }   // decode (j, i), rows of 12-j
        const int i = mm;
        const float* __restrict__ P0 = sP0[ch][j];
        const float* __restrict__ P1 = sP1[ch][i];
        float a0 = 0.f, a1 = 0.f, a2 = 0.f, a3 = 0.f;
        #pragma unroll
        for (int f = 0; f < 32; f += 4) {
            a0 = fmaf(P0[f + 0], P1[f + 0], a0);
            a1 = fmaf(P0[f + 1], P1[f + 1], a1);
            a2 = fmaf(P0[f + 2], P1[f + 2], a2);
            a3 = fmaf(P0[f + 3], P1[f + 3], a3);
        }
        g_mom[b][m][8 * r + ch] = (a0 + a1) + (a2 + a3);
    }
}

// ---------------- K2: evaluation ----------------
// grid = 128 (b = bid>>3, window r = bid&7), 1024 threads.
// sub = tid>>8: {0: h0-poly, 1: h1-poly, 2: h0-tail, 3: h1-tail}; uniform barriers.
__global__ __launch_bounds__(1024, 1)
void k2_eval(const float* __restrict__ x,
             const float* __restrict__ Wq,
             const float* __restrict__ Wk,
             const float* __restrict__ Wv,
             const float* __restrict__ Wo,
             const float* __restrict__ Wb,
             float* __restrict__ out)
{
    __shared__ float2 sY[256];          // xp window
    __shared__ float  sPre[8][NMOM];    // prefix over chunks < 8r+quad
    __shared__ float  sM[2][2][2];      // M[h][i][j]
    __shared__ float  sG[2][2];         // g[h][i]
    __shared__ float4 sPart[256][4];    // per-(c,sub) partials {den/sd, a0/s0, a1/s1}
    __shared__ float2 sO[256];          // per-head outputs

    const int tid = threadIdx.x;
    const int b   = blockIdx.x >> 3;
    const int r   = blockIdx.x & 7;

    // ---- concurrent setup: [0,256) sY | [256,448) dots | [448,526) prefixes ----
    if (tid < 256) {
        const int f = r * 256 + tid;
        const float2 v = reinterpret_cast<const float2*>(x)[b * CC + f];
        sY[tid] = make_float2(v.x + sinf((float)f), v.y + cosf((float)f));
    } else if (tid < 448) {
        const int grp = (tid - 256) >> 4, l16 = tid & 15;
        const float *pa, *pb;
        if (grp < 8) {
            const int h = grp >> 2, i = (grp >> 1) & 1, jj = grp & 1;
            pa = Wq + h * 128 + i * 64;
            pb = Wk + h * 128 + jj * 64;
        } else {
            const int g2 = grp - 8, h = g2 >> 1, i = g2 & 1;
            pa = Wv + h * 128 + i * 64;
            pb = Wo + h * 64;
        }
        float s = 0.f;
        #pragma unroll
        for (int e = 0; e < 4; ++e) s = fmaf(pa[l16 * 4 + e], pb[l16 * 4 + e], s);
        #pragma unroll
        for (int off = 8; off; off >>= 1) s += __shfl_down_sync(0xffffffffu, s, off, 16);
        if (l16 == 0) {
            if (grp < 8) sM[grp >> 2][(grp >> 1) & 1][grp & 1] = s;
            else         sG[(grp - 8) >> 1][(grp - 8) & 1]     = s;
        }
    } else if (tid < 448 + NMOM) {
        // float4 MLP prefix: chunk-contiguous g_mom rows; block-uniform bound 2r+2
        const int m = tid - 448;
        const float4* __restrict__ vp = reinterpret_cast<const float4*>(g_mom[b][m]);
        const int base = 8 * r;
        const int gmax = 2 * r + 2;     // covers k < base+8
        float s = 0.f;
        for (int g = 0; g < gmax; ++g) {
            const float4 vv = vp[g];
            const int k0 = 4 * g;
            #pragma unroll
            for (int cidx = 0; cidx < 4; ++cidx) {
                const int k = k0 + cidx;
                const float val = (cidx == 0) ? vv.x : (cidx == 1) ? vv.y
                                 : (cidx == 2) ? vv.z : vv.w;
                if (k >= base && k < base + 8) sPre[k - base][m] = s;
                if (k < base + 7) s += val;
            }
        }
    }
    __syncthreads();

    const int c_loc = tid & 255;
    const int sub   = tid >> 8;
    const int h     = sub & 1;
    const int type  = sub >> 1;         // 0 = poly, 1 = tail
    const int quad  = c_loc >> 5;       // chunk32 within window, warp-uniform

    const float2 yc = sY[c_loc];
    const float p0 = (sM[h][0][0] * yc.x + sM[h][1][0] * yc.y) * 0.125f;
    const float p1 = (sM[h][0][1] * yc.x + sM[h][1][1] * yc.y) * 0.125f;

    if (type == 0) {
        // ---- poly (row-factorized, degree 10): sums over f < 32*(8r+quad) ----
        const float INV[12] = {0.f, 1.f, 0.5f, 1.f/3.f, 0.25f, 0.2f, 1.f/6.f,
                               1.f/7.f, 0.125f, 1.f/9.f, 0.1f, 1.f/11.f};
        float aq[12], bq[12];
        aq[0] = 1.f; bq[0] = 1.f;
        #pragma unroll
        for (int t = 1; t < 12; ++t) {
            aq[t] = aq[t - 1] * p0 * INV[t];
            bq[t] = bq[t - 1] * p1 * INV[t];
        }
        const float* PRE = sPre[quad];
        float sd = 0.f, s0 = 0.f, s1 = 0.f;
        #pragma unroll
        for (int J = 0; J <= 11; ++J) {
            const int ro = J * 12 - (J * (J - 1)) / 2;
            float rt = 0.f, rs = 0.f, Plast = 0.f;
            #pragma unroll
            for (int I = 0; I + J <= 11; ++I) {
                const float P = PRE[ro + I];
                if (I + J <= 10) rt = fmaf(bq[I], P, rt);       // r_trunc (den)
                if (I >= 1)      rs = fmaf(bq[I - 1], P, rs);   // r_shift (A1)
                if (I + J == 11) Plast = P;
            }
            const float rf = fmaf(bq[11 - J], Plast, rt);       // r_full (A0)
            if (J <= 10) sd = fmaf(aq[J], rt, sd);
            if (J >= 1)  s0 = fmaf(aq[J - 1], rf, s0);
            s1 = fmaf(aq[J], rs, s1);
        }
        sPart[c_loc][sub] = make_float4(sd, s0, s1, 0.f);
    } else {
        // ---- exact tail over f in [32*chunk(c), c]  (<= 32 iterations) ----
        const float pd0 = p0 * LOG2E, pd1 = p1 * LOG2E;
        float den = 0.f, a0 = 0.f, a1 = 0.f;
        for (int fl = c_loc & ~31; fl <= c_loc; ++fl) {
            const float2 yf = sY[fl];
            const float e = ex2f(fmaf(yf.x, pd0, yf.y * pd1));
            den += e; a0 = fmaf(e, yf.x, a0); a1 = fmaf(e, yf.y, a1);
        }
        sPart[c_loc][sub] = make_float4(den, a0, a1, 0.f);
    }
    __syncthreads();

    if (type == 0) {
        const float4 mine = sPart[c_loc][sub];
        const float4 tt   = sPart[c_loc][2 + h];
        const float den = mine.x + tt.x;
        const float A0  = mine.y + tt.y;
        const float A1  = mine.z + tt.z;
        const float o   = (sG[h][0] * A0 + sG[h][1] * A1) / den;
        if (h == 0) sO[c_loc].x = o; else sO[c_loc].y = o;
    }
    __syncthreads();

    if (tid < 256) {
        const float2 o = sO[tid];
        const float b00 = __ldg(Wb + 0), b01 = __ldg(Wb + 1);
        const float b10 = __ldg(Wb + 2), b11 = __ldg(Wb + 3);
        float2 res;
        res.x = fmaf(o.x, b00, o.y * b10);
        res.y = fmaf(o.x, b01, o.y * b11);
        reinterpret_cast<float2*>(out)[b * CC + r * 256 + tid] = res;
    }
}

extern "C" void kernel_launch(void* const* d_in, const int* in_sizes, int n_in,
                              void* d_out, int out_size)
{
    const float* x  = (const float*)d_in[0];
    const float* Wq = (const float*)d_in[1];
    const float* Wk = (const float*)d_in[2];
    const float* Wv = (const float*)d_in[3];
    const float* Wo = (const float*)d_in[4];
    const float* Wb = (const float*)d_in[5];
    float* out = (float*)d_out;

    k1_moments<<<128, 640>>>(x);
    k2_eval<<<128, 1024>>>(x, Wq, Wk, Wv, Wo, Wb, out);
}

// round 13
// speedup vs baseline: 1.3123x; 1.3123x over previous
#include <cuda_runtime.h>

// B=16, C=2048, H=2, HS=64, HOD=1, D_MODEL=2
// Collapsed: M_h = Wq_h Wk_h^T (2x2), g_h = Wv_h Wo_h (2,)
//   t(c,f) = xp_c^T M_h xp_f / 8;  o_h(c) = sum_{f<=c} e^t (g_h.xp_f) / sum e^t
// Taylor degree 10: e^{p.y} = sum_{j+i<=10} (p0^j/j!)(p1^i/i!) y0^j y1^i
// => causal sums = polynomial in prefix moments M_{j,i} = sum_f y0^j y1^i (j+i<=11).
// Chunk = 64 f (32 chunks). R11 skeleton: K1 power-table dots; K2 with v[32]
// unconditional MLP prefix, row-factored degree-10 poly, exact tails <= 64.

#define CC    2048
#define NMOM  78            // #{(j,i): j+i<=11}
#define LOG2E 1.4426950408889634f

__device__ float g_mom[16][32][NMOM];   // per (batch, chunk64) raw moments

__device__ __forceinline__ float ex2f(float v) {
    float y;
    asm("ex2.approx.ftz.f32 %0, %1;" : "=f"(y) : "f"(v));
    return y;
}

// ---------------- K1: chunk moments via smem power tables ----------------
// grid = 128 (b = bid>>3, window r = bid&7), 512 threads.
__global__ __launch_bounds__(512, 1)
void k1_moments(const float* __restrict__ x)
{
    __shared__ float sP0[4][12][67];   // y0^j per chunk64, pad 67 (conflict-free)
    __shared__ float sP1[4][12][67];   // y1^i

    const int tid = threadIdx.x;
    const int b   = blockIdx.x >> 3;
    const int r   = blockIdx.x & 7;

    if (tid < 256) {
        const int ch = tid >> 6, fl = tid & 63;
        const int f  = r * 256 + tid;
        const float2 v = reinterpret_cast<const float2*>(x)[b * CC + f];
        const float y0 = v.x + sinf((float)f);
        const float y1 = v.y + cosf((float)f);
        float p = 1.f, q = 1.f;
        #pragma unroll
        for (int j = 0; j < 12; ++j) {
            sP0[ch][j][fl] = p;  p *= y0;
            sP1[ch][j][fl] = q;  q *= y1;
        }
    }
    __syncthreads();

    if (tid < 4 * NMOM) {              // 312 dot threads
        const int ch = tid / NMOM;
        const int m  = tid % NMOM;
        int j = 0, mm = m;
        while (mm >= 12 - j) { mm -= 12 - j; ++j; }   // decode (j, i), rows of 12-j
        const int i = mm;
        const float* __restrict__ P0 = sP0[ch][j];
        const float* __restrict__ P1 = sP1[ch][i];
        float a0 = 0.f, a1 = 0.f, a2 = 0.f, a3 = 0.f;
        #pragma unroll
        for (int f = 0; f < 64; f += 4) {
            a0 = fmaf(P0[f + 0], P1[f + 0], a0);
            a1 = fmaf(P0[f + 1], P1[f + 1], a1);
            a2 = fmaf(P0[f + 2], P1[f + 2], a2);
            a3 = fmaf(P0[f + 3], P1[f + 3], a3);
        }
        g_mom[b][4 * r + ch][m] = (a0 + a1) + (a2 + a3);
    }
}

// ---------------- K2: evaluation ----------------
// grid = 128 (b = bid>>3, window r = bid&7), 1024 threads.
// sub = tid>>8: {0: h0-poly, 1: h1-poly, 2: h0-tail, 3: h1-tail}; uniform barriers.
__global__ __launch_bounds__(1024, 1)
void k2_eval(const float* __restrict__ x,
             const float* __restrict__ Wq,
             const float* __restrict__ Wk,
             const float* __restrict__ Wv,
             const float* __restrict__ Wo,
             const float* __restrict__ Wb,
             float* __restrict__ out)
{
    __shared__ float2 sY[256];          // xp window
    __shared__ float  sPre[4][NMOM];    // prefix over chunks < 4r+quad
    __shared__ float  sM[2][2][2];      // M[h][i][j]
    __shared__ float  sG[2][2];         // g[h][i]
    __shared__ float4 sPart[256][4];    // per-(c,sub) partials {den/sd, a0/s0, a1/s1}
    __shared__ float2 sO[256];          // per-head outputs

    const int tid = threadIdx.x;
    const int b   = blockIdx.x >> 3;
    const int r   = blockIdx.x & 7;

    // ---- concurrent setup: [0,256) sY | [256,448) dots | [448,526) prefixes ----
    if (tid < 256) {
        const int f = r * 256 + tid;
        const float2 v = reinterpret_cast<const float2*>(x)[b * CC + f];
        sY[tid] = make_float2(v.x + sinf((float)f), v.y + cosf((float)f));
    } else if (tid < 448) {
        const int grp = (tid - 256) >> 4, l16 = tid & 15;
        const float *pa, *pb;
        if (grp < 8) {
            const int h = grp >> 2, i = (grp >> 1) & 1, jj = grp & 1;
            pa = Wq + h * 128 + i * 64;
            pb = Wk + h * 128 + jj * 64;
        } else {
            const int g2 = grp - 8, h = g2 >> 1, i = g2 & 1;
            pa = Wv + h * 128 + i * 64;
            pb = Wo + h * 64;
        }
        float s = 0.f;
        #pragma unroll
        for (int e = 0; e < 4; ++e) s = fmaf(pa[l16 * 4 + e], pb[l16 * 4 + e], s);
        #pragma unroll
        for (int off = 8; off; off >>= 1) s += __shfl_down_sync(0xffffffffu, s, off, 16);
        if (l16 == 0) {
            if (grp < 8) sM[grp >> 2][(grp >> 1) & 1][grp & 1] = s;
            else         sG[(grp - 8) >> 1][(grp - 8) & 1]     = s;
        }
    } else if (tid < 448 + NMOM) {
        // MLP prefix: unconditional preload of all 32 chunk values, then scan
        const int m = tid - 448;
        float v[32];
        #pragma unroll
        for (int k = 0; k < 32; ++k) v[k] = g_mom[b][k][m];
        float s = 0.f;
        const int base = 4 * r;
        #pragma unroll
        for (int k = 0; k < 32; ++k) {
            if (k >= base && k < base + 4) sPre[k - base][m] = s;
            if (k < base + 3) s += v[k];
        }
    }
    __syncthreads();

    const int c_loc = tid & 255;
    const int sub   = tid >> 8;
    const int h     = sub & 1;
    const int type  = sub >> 1;         // 0 = poly, 1 = tail
    const int quad  = c_loc >> 6;       // chunk64 within window, warp-uniform

    const float2 yc = sY[c_loc];
    const float p0 = (sM[h][0][0] * yc.x + sM[h][1][0] * yc.y) * 0.125f;
    const float p1 = (sM[h][0][1] * yc.x + sM[h][1][1] * yc.y) * 0.125f;

    if (type == 0) {
        // ---- poly (row-factorized, degree 10): sums over f < 64*(4r+quad) ----
        const float INV[12] = {0.f, 1.f, 0.5f, 1.f/3.f, 0.25f, 0.2f, 1.f/6.f,
                               1.f/7.f, 0.125f, 1.f/9.f, 0.1f, 1.f/11.f};
        float aq[12], bq[12];
        aq[0] = 1.f; bq[0] = 1.f;
        #pragma unroll
        for (int t = 1; t < 12; ++t) {
            aq[t] = aq[t - 1] * p0 * INV[t];
            bq[t] = bq[t - 1] * p1 * INV[t];
        }
        const float* PRE = sPre[quad];
        float sd = 0.f, s0 = 0.f, s1 = 0.f;
        #pragma unroll
        for (int J = 0; J <= 11; ++J) {
            const int ro = J * 12 - (J * (J - 1)) / 2;
            float rt = 0.f, rs = 0.f, Plast = 0.f;
            #pragma unroll
            for (int I = 0; I + J <= 11; ++I) {
                const float P = PRE[ro + I];
                if (I + J <= 10) rt = fmaf(bq[I], P, rt);       // r_trunc (den)
                if (I >= 1)      rs = fmaf(bq[I - 1], P, rs);   // r_shift (A1)
                if (I + J == 11) Plast = P;
            }
            const float rf = fmaf(bq[11 - J], Plast, rt);       // r_full (A0)
            if (J <= 10) sd = fmaf(aq[J], rt, sd);
            if (J >= 1)  s0 = fmaf(aq[J - 1], rf, s0);
            s1 = fmaf(aq[J], rs, s1);
        }
        sPart[c_loc][sub] = make_float4(sd, s0, s1, 0.f);
    } else {
        // ---- exact tail over f in [64*chunk(c), c]  (<= 64 iterations) ----
        const float pd0 = p0 * LOG2E, pd1 = p1 * LOG2E;
        float den = 0.f, a0 = 0.f, a1 = 0.f;
        for (int fl = c_loc & ~63; fl <= c_loc; ++fl) {
            const float2 yf = sY[fl];
            const float e = ex2f(fmaf(yf.x, pd0, yf.y * pd1));
            den += e; a0 = fmaf(e, yf.x, a0); a1 = fmaf(e, yf.y, a1);
        }
        sPart[c_loc][sub] = make_float4(den, a0, a1, 0.f);
    }
    __syncthreads();

    if (type == 0) {
        const float4 mine = sPart[c_loc][sub];
        const float4 tt   = sPart[c_loc][2 + h];
        const float den = mine.x + tt.x;
        const float A0  = mine.y + tt.y;
        const float A1  = mine.z + tt.z;
        const float o   = (sG[h][0] * A0 + sG[h][1] * A1) / den;
        if (h == 0) sO[c_loc].x = o; else sO[c_loc].y = o;
    }
    __syncthreads();

    if (tid < 256) {
        const float2 o = sO[tid];
        const float b00 = __ldg(Wb + 0), b01 = __ldg(Wb + 1);
        const float b10 = __ldg(Wb + 2), b11 = __ldg(Wb + 3);
        float2 res;
        res.x = fmaf(o.x, b00, o.y * b10);
        res.y = fmaf(o.x, b01, o.y * b11);
        reinterpret_cast<float2*>(out)[b * CC + r * 256 + tid] = res;
    }
}

extern "C" void kernel_launch(void* const* d_in, const int* in_sizes, int n_in,
                              void* d_out, int out_size)
{
    const float* x  = (const float*)d_in[0];
    const float* Wq = (const float*)d_in[1];
    const float* Wk = (const float*)d_in[2];
    const float* Wv = (const float*)d_in[3];
    const float* Wo = (const float*)d_in[4];
    const float* Wb = (const float*)d_in[5];
    float* out = (float*)d_out;

    k1_moments<<<128, 512>>>(x);
    k2_eval<<<128, 1024>>>(x, Wq, Wk, Wv, Wo, Wb, out);
}

// round 14
// speedup vs baseline: 1.3283x; 1.0122x over previous
#include <cuda_runtime.h>

// B=16, C=2048, H=2, HS=64, HOD=1, D_MODEL=2
// Collapsed: M_h = Wq_h Wk_h^T (2x2), g_h = Wv_h Wo_h (2,)
//   t(c,f) = xp_c^T M_h xp_f / 8;  o_h(c) = sum_{f<=c} e^t (g_h.xp_f) / sum e^t
// Taylor degree 10: e^{p.y} = sum_{j+i<=10} (p0^j/j!)(p1^i/i!) y0^j y1^i
// => causal sums = polynomial in prefix moments M_{j,i} = sum_f y0^j y1^i (j+i<=11).
// Chunk = 64 f (32 chunks). K1 power-table dots -> g_mom. K2: v[32] MLP prefix,
// row-factored degree-10 poly, exact tails <= 64. NEW: PDL overlap — K2 launches
// with ProgrammaticStreamSerialization; only its prefix loaders griddepcontrol.wait,
// so K2's sY/sinf/dot setup runs concurrently with K1. Epilogue folded (one stage).

#define CC    2048
#define NMOM  78            // #{(j,i): j+i<=11}
#define LOG2E 1.4426950408889634f

__device__ float g_mom[16][32][NMOM];   // per (batch, chunk64) raw moments

__device__ __forceinline__ float ex2f(float v) {
    float y;
    asm("ex2.approx.ftz.f32 %0, %1;" : "=f"(y) : "f"(v));
    return y;
}

// ---------------- K1: chunk moments via smem power tables ----------------
// grid = 128 (b = bid>>3, window r = bid&7), 512 threads.
__global__ __launch_bounds__(512, 1)
void k1_moments(const float* __restrict__ x)
{
    __shared__ float sP0[4][12][67];   // y0^j per chunk64, pad 67 (conflict-free)
    __shared__ float sP1[4][12][67];   // y1^i

    const int tid = threadIdx.x;
    const int b   = blockIdx.x >> 3;
    const int r   = blockIdx.x & 7;

    if (tid < 256) {
        const int ch = tid >> 6, fl = tid & 63;
        const int f  = r * 256 + tid;
        const float2 v = reinterpret_cast<const float2*>(x)[b * CC + f];
        const float y0 = v.x + sinf((float)f);
        const float y1 = v.y + cosf((float)f);
        float p = 1.f, q = 1.f;
        #pragma unroll
        for (int j = 0; j < 12; ++j) {
            sP0[ch][j][fl] = p;  p *= y0;
            sP1[ch][j][fl] = q;  q *= y1;
        }
    }
    __syncthreads();

    if (tid < 4 * NMOM) {              // 312 dot threads
        const int ch = tid / NMOM;
        const int m  = tid % NMOM;
        int j = 0, mm = m;
        while (mm >= 12 - j) { mm -= 12 - j; ++j; }   // decode (j, i), rows of 12-j
        const int i = mm;
        const float* __restrict__ P0 = sP0[ch][j];
        const float* __restrict__ P1 = sP1[ch][i];
        float a0 = 0.f, a1 = 0.f, a2 = 0.f, a3 = 0.f;
        #pragma unroll
        for (int f = 0; f < 64; f += 4) {
            a0 = fmaf(P0[f + 0], P1[f + 0], a0);
            a1 = fmaf(P0[f + 1], P1[f + 1], a1);
            a2 = fmaf(P0[f + 2], P1[f + 2], a2);
            a3 = fmaf(P0[f + 3], P1[f + 3], a3);
        }
        g_mom[b][4 * r + ch][m] = (a0 + a1) + (a2 + a3);
    }

    // publish: make g_mom visible, then allow the dependent grid to consume
    __syncthreads();
    __threadfence();
    asm volatile("griddepcontrol.launch_dependents;" ::: "memory");
}

// ---------------- K2: evaluation ----------------
// grid = 128 (b = bid>>3, window r = bid&7), 1024 threads.
// sub = tid>>8: {0: h0-poly, 1: h1-poly, 2: h0-tail, 3: h1-tail}; uniform barriers.
__global__ __launch_bounds__(1024, 1)
void k2_eval(const float* __restrict__ x,
             const float* __restrict__ Wq,
             const float* __restrict__ Wk,
             const float* __restrict__ Wv,
             const float* __restrict__ Wo,
             const float* __restrict__ Wb,
             float* __restrict__ out)
{
    __shared__ float2 sY[256];          // xp window
    __shared__ float  sPre[4][NMOM];    // prefix over chunks < 4r+quad
    __shared__ float  sM[2][2][2];      // M[h][i][j]
    __shared__ float  sG[2][2];         // g[h][i]
    __shared__ float4 sPart[256][4];    // per-(c,sub) partials {den/sd, a0/s0, a1/s1}

    const int tid = threadIdx.x;
    const int b   = blockIdx.x >> 3;
    const int r   = blockIdx.x & 7;

    // ---- concurrent setup: [0,256) sY | [256,448) dots | [448,526) prefixes ----
    // Only the prefix branch depends on K1 (g_mom); it alone waits on the grid dep.
    if (tid < 256) {
        const int f = r * 256 + tid;
        const float2 v = reinterpret_cast<const float2*>(x)[b * CC + f];
        sY[tid] = make_float2(v.x + sinf((float)f), v.y + cosf((float)f));
    } else if (tid < 448) {
        const int grp = (tid - 256) >> 4, l16 = tid & 15;
        const float *pa, *pb;
        if (grp < 8) {
            const int h = grp >> 2, i = (grp >> 1) & 1, jj = grp & 1;
            pa = Wq + h * 128 + i * 64;
            pb = Wk + h * 128 + jj * 64;
        } else {
            const int g2 = grp - 8, h = g2 >> 1, i = g2 & 1;
            pa = Wv + h * 128 + i * 64;
            pb = Wo + h * 64;
        }
        float s = 0.f;
        #pragma unroll
        for (int e = 0; e < 4; ++e) s = fmaf(pa[l16 * 4 + e], pb[l16 * 4 + e], s);
        #pragma unroll
        for (int off = 8; off; off >>= 1) s += __shfl_down_sync(0xffffffffu, s, off, 16);
        if (l16 == 0) {
            if (grp < 8) sM[grp >> 2][(grp >> 1) & 1][grp & 1] = s;
            else         sG[(grp - 8) >> 1][(grp - 8) & 1]     = s;
        }
    } else if (tid < 448 + NMOM) {
        asm volatile("griddepcontrol.wait;" ::: "memory");   // K1 done/published
        // MLP prefix: unconditional preload of all 32 chunk values, then scan
        const int m = tid - 448;
        float v[32];
        #pragma unroll
        for (int k = 0; k < 32; ++k) v[k] = g_mom[b][k][m];
        float s = 0.f;
        const int base = 4 * r;
        #pragma unroll
        for (int k = 0; k < 32; ++k) {
            if (k >= base && k < base + 4) sPre[k - base][m] = s;
            if (k < base + 3) s += v[k];
        }
    }
    __syncthreads();

    const int c_loc = tid & 255;
    const int sub   = tid >> 8;
    const int h     = sub & 1;
    const int type  = sub >> 1;         // 0 = poly, 1 = tail
    const int quad  = c_loc >> 6;       // chunk64 within window, warp-uniform

    const float2 yc = sY[c_loc];
    const float p0 = (sM[h][0][0] * yc.x + sM[h][1][0] * yc.y) * 0.125f;
    const float p1 = (sM[h][0][1] * yc.x + sM[h][1][1] * yc.y) * 0.125f;

    if (type == 0) {
        // ---- poly (row-factorized, degree 10): sums over f < 64*(4r+quad) ----
        const float INV[12] = {0.f, 1.f, 0.5f, 1.f/3.f, 0.25f, 0.2f, 1.f/6.f,
                               1.f/7.f, 0.125f, 1.f/9.f, 0.1f, 1.f/11.f};
        float aq[12], bq[12];
        aq[0] = 1.f; bq[0] = 1.f;
        #pragma unroll
        for (int t = 1; t < 12; ++t) {
            aq[t] = aq[t - 1] * p0 * INV[t];
            bq[t] = bq[t - 1] * p1 * INV[t];
        }
        const float* PRE = sPre[quad];
        float sd = 0.f, s0 = 0.f, s1 = 0.f;
        #pragma unroll
        for (int J = 0; J <= 11; ++J) {
            const int ro = J * 12 - (J * (J - 1)) / 2;
            float rt = 0.f, rs = 0.f, Plast = 0.f;
            #pragma unroll
            for (int I = 0; I + J <= 11; ++I) {
                const float P = PRE[ro + I];
                if (I + J <= 10) rt = fmaf(bq[I], P, rt);       // r_trunc (den)
                if (I >= 1)      rs = fmaf(bq[I - 1], P, rs);   // r_shift (A1)
                if (I + J == 11) Plast = P;
            }
            const float rf = fmaf(bq[11 - J], Plast, rt);       // r_full (A0)
            if (J <= 10) sd = fmaf(aq[J], rt, sd);
            if (J >= 1)  s0 = fmaf(aq[J - 1], rf, s0);
            s1 = fmaf(aq[J], rs, s1);
        }
        sPart[c_loc][sub] = make_float4(sd, s0, s1, 0.f);
    } else {
        // ---- exact tail over f in [64*chunk(c), c]  (<= 64 iterations) ----
        const float pd0 = p0 * LOG2E, pd1 = p1 * LOG2E;
        float den = 0.f, a0 = 0.f, a1 = 0.f;
        for (int fl = c_loc & ~63; fl <= c_loc; ++fl) {
            const float2 yf = sY[fl];
            const float e = ex2f(fmaf(yf.x, pd0, yf.y * pd1));
            den += e; a0 = fmaf(e, yf.x, a0); a1 = fmaf(e, yf.y, a1);
        }
        sPart[c_loc][sub] = make_float4(den, a0, a1, 0.f);
    }
    __syncthreads();

    // ---- folded epilogue: sub 0 combines both heads and writes out ----
    if (sub == 0) {
        const float4 P0h = sPart[c_loc][0];   // h0 poly
        const float4 P1h = sPart[c_loc][1];   // h1 poly
        const float4 T0h = sPart[c_loc][2];   // h0 tail
        const float4 T1h = sPart[c_loc][3];   // h1 tail
        const float o0 = (sG[0][0] * (P0h.y + T0h.y) + sG[0][1] * (P0h.z + T0h.z))
                         / (P0h.x + T0h.x);
        const float o1 = (sG[1][0] * (P1h.y + T1h.y) + sG[1][1] * (P1h.z + T1h.z))
                         / (P1h.x + T1h.x);
        const float b00 = __ldg(Wb + 0), b01 = __ldg(Wb + 1);
        const float b10 = __ldg(Wb + 2), b11 = __ldg(Wb + 3);
        float2 res;
        res.x = fmaf(o0, b00, o1 * b10);
        res.y = fmaf(o0, b01, o1 * b11);
        reinterpret_cast<float2*>(out)[b * CC + r * 256 + c_loc] = res;
    }
}

extern "C" void kernel_launch(void* const* d_in, const int* in_sizes, int n_in,
                              void* d_out, int out_size)
{
    const float* x  = (const float*)d_in[0];
    const float* Wq = (const float*)d_in[1];
    const float* Wk = (const float*)d_in[2];
    const float* Wv = (const float*)d_in[3];
    const float* Wo = (const float*)d_in[4];
    const float* Wb = (const float*)d_in[5];
    float* out = (float*)d_out;

    k1_moments<<<128, 512>>>(x);

    // K2 with programmatic stream serialization: it may begin while K1 runs;
    // its g_mom consumers gate on griddepcontrol.wait.
    cudaLaunchConfig_t cfg = {};
    cfg.gridDim  = dim3(128);
    cfg.blockDim = dim3(1024);
    cudaLaunchAttribute attrs[1];
    attrs[0].id = cudaLaunchAttributeProgrammaticStreamSerialization;
    attrs[0].val.programmaticStreamSerializationAllowed = 1;
    cfg.attrs    = attrs;
    cfg.numAttrs = 1;
    cudaLaunchKernelEx(&cfg, k2_eval, x, Wq, Wk, Wv, Wo, Wb, out);
}